// round 3
// baseline (speedup 1.0000x reference)
#include <cuda_runtime.h>
#include <cstdint>

#define N_TOK   49
#define C_DIM   256
#define H_NUM   8
#define HD      32
#define B_WIN   4096
#define NW_MASK 63
#define M_ROWS  (B_WIN * N_TOK)   // 200704
#define QKV_N   (3 * C_DIM)       // 768

// Scratch (allocation-free rule: __device__ globals)
__device__ float g_qkv[(size_t)B_WIN * H_NUM * 3 * N_TOK * HD];   // 616 MB
__device__ float g_attn[(size_t)M_ROWS * C_DIM];                  // 205 MB

// ---------------------------------------------------------------------------
__device__ __forceinline__ float to_tf32(float x) {
    uint32_t u;
    asm("cvt.rna.tf32.f32 %0, %1;" : "=r"(u) : "f"(x));
    return __uint_as_float(u);
}

__device__ __forceinline__ void mma_tf32(float c[4], const uint32_t a[4], const uint32_t b[2]) {
    asm volatile(
        "mma.sync.aligned.m16n8k8.row.col.f32.tf32.tf32.f32 "
        "{%0,%1,%2,%3}, {%4,%5,%6,%7}, {%8,%9}, {%0,%1,%2,%3};"
        : "+f"(c[0]), "+f"(c[1]), "+f"(c[2]), "+f"(c[3])
        : "r"(a[0]), "r"(a[1]), "r"(a[2]), "r"(a[3]), "r"(b[0]), "r"(b[1]));
}

// ---------------------------------------------------------------------------
// X-resident GEMM: X tile [128 x 256] lives in smem for the whole kernel;
// N is processed in 64-col chunks with a double-buffered 32-deep W slab.
//   QKV_MODE=true : X = input x, epilogue scatters (bias+scale) into g_qkv
//   QKV_MODE=false: X = g_attn,  epilogue writes (bias) to out
// dynamic smem: Xs[128][260] + Bs[2][64][36] = 151552 B  (1 CTA/SM)
// ---------------------------------------------------------------------------
#define XS_STRIDE 260   // 260 % 32 == 4 -> conflict-free fragment LDS
#define GEMM_SMEM (128 * XS_STRIDE * 4 + 2 * 64 * 36 * 4)

template<int NCHUNKS, bool QKV_MODE>
__global__ __launch_bounds__(256) void gemm_xres(
    const float* __restrict__ Xin, const float* __restrict__ W,
    const float* __restrict__ bias, float* __restrict__ out)
{
    extern __shared__ float sm[];
    float (*Xs)[XS_STRIDE] = (float(*)[XS_STRIDE])sm;
    float (*Bs)[64][36]    = (float(*)[64][36])(sm + 128 * XS_STRIDE);

    const int tid   = threadIdx.x;
    const int mBase = blockIdx.x * 128;
    const float* X = QKV_MODE ? Xin : (const float*)g_attn;

    // stage X tile (tf32-converted): 8192 float4, 32 per thread
#pragma unroll
    for (int p = 0; p < 32; p++) {
        int idx = tid + p * 256;
        int r = idx >> 6;
        int c = (idx & 63) * 4;
        float4 v = *(const float4*)(X + (size_t)(mBase + r) * C_DIM + c);
        Xs[r][c + 0] = to_tf32(v.x); Xs[r][c + 1] = to_tf32(v.y);
        Xs[r][c + 2] = to_tf32(v.z); Xs[r][c + 3] = to_tf32(v.w);
    }

    const int warp = tid >> 5, lane = tid & 31;
    const int wm = (warp & 3) * 32, wn = (warp >> 2) * 32;
    const int g = lane >> 2, t = lane & 3;
    const float qscale = 0.17677669529663687f;

    for (int nc = 0; nc < NCHUNKS; nc++) {
        const int nBase = nc * 64;

        // load k-slab 0 (W rows nBase..+63, k 0..31)
#pragma unroll
        for (int u = 0; u < 2; u++) {
            int idx = tid * 2 + u;
            int r = idx >> 3;
            int c = (idx & 7) * 4;
            float4 v = *(const float4*)(W + (size_t)(nBase + r) * C_DIM + c);
            Bs[0][r][c + 0] = to_tf32(v.x); Bs[0][r][c + 1] = to_tf32(v.y);
            Bs[0][r][c + 2] = to_tf32(v.z); Bs[0][r][c + 3] = to_tf32(v.w);
        }
        __syncthreads();

        float acc[2][4][4] = {};

        for (int ks = 0; ks < 8; ks++) {
            const int cur = ks & 1;
            float4 pf[2];
            int pr[2], pc[2];
            if (ks < 7) {
#pragma unroll
                for (int u = 0; u < 2; u++) {
                    int idx = tid * 2 + u;
                    pr[u] = idx >> 3;
                    pc[u] = (idx & 7) * 4;
                    pf[u] = *(const float4*)(W + (size_t)(nBase + pr[u]) * C_DIM
                                             + (ks + 1) * 32 + pc[u]);
                }
            }
#pragma unroll
            for (int ko = 0; ko < 32; ko += 8) {
                const int kg = ks * 32 + ko;
                uint32_t a[2][4], bb[4][2];
#pragma unroll
                for (int mi = 0; mi < 2; mi++) {
                    int row = wm + mi * 16 + g;
                    a[mi][0] = __float_as_uint(Xs[row][kg + t]);
                    a[mi][1] = __float_as_uint(Xs[row + 8][kg + t]);
                    a[mi][2] = __float_as_uint(Xs[row][kg + t + 4]);
                    a[mi][3] = __float_as_uint(Xs[row + 8][kg + t + 4]);
                }
#pragma unroll
                for (int ni = 0; ni < 4; ni++) {
                    int col = wn + ni * 8 + g;
                    bb[ni][0] = __float_as_uint(Bs[cur][col][ko + t]);
                    bb[ni][1] = __float_as_uint(Bs[cur][col][ko + t + 4]);
                }
#pragma unroll
                for (int mi = 0; mi < 2; mi++)
#pragma unroll
                    for (int ni = 0; ni < 4; ni++)
                        mma_tf32(acc[mi][ni], a[mi], bb[ni]);
            }
            if (ks < 7) {
                const int nxt = cur ^ 1;
#pragma unroll
                for (int u = 0; u < 2; u++) {
                    Bs[nxt][pr[u]][pc[u] + 0] = to_tf32(pf[u].x);
                    Bs[nxt][pr[u]][pc[u] + 1] = to_tf32(pf[u].y);
                    Bs[nxt][pr[u]][pc[u] + 2] = to_tf32(pf[u].z);
                    Bs[nxt][pr[u]][pc[u] + 3] = to_tf32(pf[u].w);
                }
            }
            __syncthreads();
        }

        // epilogue for this n-chunk
#pragma unroll
        for (int mi = 0; mi < 2; mi++) {
#pragma unroll
            for (int ni = 0; ni < 4; ni++) {
                int gn = nBase + wn + ni * 8 + t * 2;
                float bv0 = bias[gn], bv1 = bias[gn + 1];
                if (QKV_MODE) {
                    int which = gn >> 8;          // 0:q 1:k 2:v
                    int h = (gn >> 5) & 7;
                    int d = gn & 31;
                    float sc = (which == 0) ? qscale : 1.0f;
#pragma unroll
                    for (int half = 0; half < 2; half++) {
                        int gm = mBase + wm + mi * 16 + g + half * 8;
                        int b = gm / 49;
                        int r = gm - b * 49;
                        float v0 = (acc[mi][ni][half * 2 + 0] + bv0) * sc;
                        float v1 = (acc[mi][ni][half * 2 + 1] + bv1) * sc;
                        size_t off = ((((size_t)b * 8 + h) * 3 + which) * 49 + r) * 32 + d;
                        *(float2*)(g_qkv + off) = make_float2(v0, v1);
                    }
                } else {
#pragma unroll
                    for (int half = 0; half < 2; half++) {
                        int gm = mBase + wm + mi * 16 + g + half * 8;
                        float v0 = acc[mi][ni][half * 2 + 0] + bv0;
                        float v1 = acc[mi][ni][half * 2 + 1] + bv1;
                        *(float2*)(out + (size_t)gm * C_DIM + gn) = make_float2(v0, v1);
                    }
                }
            }
        }
        // Bs[0] of next chunk was last read at ks==6 (already sync'd) -> safe
    }
}

// ---------------------------------------------------------------------------
// Kernel 2: per-(window, head) attention. grid = 32768, block = 256 (8 warps)
// Warps 0..6 each own 7 rows. sS padded to 52 for float4 broadcasts.
// ---------------------------------------------------------------------------
__global__ __launch_bounds__(256) void attn_kernel(
    const float* __restrict__ mask, const float* __restrict__ bt)
{
    const int bh = blockIdx.x;
    const int b = bh >> 3;
    const int h = bh & 7;

    __shared__ float sq[N_TOK * HD];       // [i][d]
    __shared__ float skT[HD * N_TOK];      // [d][j]
    __shared__ float sv[N_TOK * HD];       // [j][d]
    __shared__ float sS[N_TOK][52];        // padded rows (52*4 % 16 == 0)

    const int tid = threadIdx.x;
    const float* base = g_qkv + (size_t)bh * 3 * (N_TOK * HD);

    for (int idx = tid; idx < 392; idx += 256)
        ((float4*)sq)[idx] = ((const float4*)base)[idx];
    for (int idx = tid; idx < 392; idx += 256) {
        float4 v = ((const float4*)(base + N_TOK * HD))[idx];
        int j = idx >> 3;
        int d = (idx & 7) * 4;
        skT[(d + 0) * N_TOK + j] = v.x;
        skT[(d + 1) * N_TOK + j] = v.y;
        skT[(d + 2) * N_TOK + j] = v.z;
        skT[(d + 3) * N_TOK + j] = v.w;
    }
    for (int idx = tid; idx < 392; idx += 256)
        ((float4*)sv)[idx] = ((const float4*)(base + 2 * N_TOK * HD))[idx];
    __syncthreads();

    const int w = tid >> 5, lane = tid & 31;
    const int i0 = w * 7;

    // S = q @ k^T
    if (i0 < N_TOK) {
        float accA[7] = {}, accB[7] = {};
#pragma unroll
        for (int d0 = 0; d0 < HD; d0 += 4) {
            float kA[4], kB[4];
#pragma unroll
            for (int dd = 0; dd < 4; dd++) {
                kA[dd] = skT[(d0 + dd) * N_TOK + lane];
                kB[dd] = (lane < 17) ? skT[(d0 + dd) * N_TOK + 32 + lane] : 0.0f;
            }
#pragma unroll
            for (int r = 0; r < 7; r++) {
                float4 qv = *(const float4*)(sq + (i0 + r) * HD + d0);
                accA[r] += qv.x * kA[0] + qv.y * kA[1] + qv.z * kA[2] + qv.w * kA[3];
                accB[r] += qv.x * kB[0] + qv.y * kB[1] + qv.z * kB[2] + qv.w * kB[3];
            }
        }
        const float* mrow = mask + (size_t)(b & NW_MASK) * (N_TOK * N_TOK);
#pragma unroll
        for (int r = 0; r < 7; r++) {
            int i = i0 + r;
            int ri = i / 7, ci = i - ri * 7;
            {
                int j = lane;
                int rj = j / 7, cj = j - rj * 7;
                int bidx = (ri - rj + 6) * 13 + (ci - cj + 6);
                sS[i][j] = accA[r] + bt[bidx * 8 + h] + mrow[i * N_TOK + j];
            }
            int j2 = lane + 32;
            if (j2 < N_TOK) {
                int rj = j2 / 7, cj = j2 - rj * 7;
                int bidx = (ri - rj + 6) * 13 + (ci - cj + 6);
                sS[i][j2] = accB[r] + bt[bidx * 8 + h] + mrow[i * N_TOK + j2];
            }
        }
    }
    __syncthreads();

    // warp-parallel softmax: warp w handles rows i0..i0+6, lanes over columns
    if (i0 < N_TOK) {
#pragma unroll
        for (int r = 0; r < 7; r++) {
            float* row = sS[i0 + r];
            float v1 = row[lane];
            float v2 = (lane < 17) ? row[32 + lane] : -1e30f;
            float m = fmaxf(v1, v2);
#pragma unroll
            for (int off = 16; off > 0; off >>= 1)
                m = fmaxf(m, __shfl_xor_sync(0xffffffffu, m, off));
            float e1 = __expf(v1 - m);
            float e2 = (lane < 17) ? __expf(v2 - m) : 0.0f;
            float s = e1 + e2;
#pragma unroll
            for (int off = 16; off > 0; off >>= 1)
                s += __shfl_xor_sync(0xffffffffu, s, off);
            float inv = __frcp_rn(s);
            row[lane] = e1 * inv;
            if (lane < 17) row[32 + lane] = e2 * inv;
        }
    }
    __syncthreads();

    // out = P @ v ; lanes over d
    if (i0 < N_TOK) {
        float acc[7] = {};
#pragma unroll
        for (int j0 = 0; j0 < 48; j0 += 4) {
            float vv[4];
#pragma unroll
            for (int dd = 0; dd < 4; dd++)
                vv[dd] = sv[(j0 + dd) * HD + lane];
#pragma unroll
            for (int r = 0; r < 7; r++) {
                float4 p = *(const float4*)(&sS[i0 + r][j0]);
                acc[r] += p.x * vv[0] + p.y * vv[1] + p.z * vv[2] + p.w * vv[3];
            }
        }
        float vv48 = sv[48 * HD + lane];
#pragma unroll
        for (int r = 0; r < 7; r++)
            acc[r] += sS[i0 + r][48] * vv48;

        float* outp = g_attn + ((size_t)b * N_TOK) * C_DIM + h * HD + lane;
#pragma unroll
        for (int r = 0; r < 7; r++)
            outp[(size_t)(i0 + r) * C_DIM] = acc[r];
    }
}

// ---------------------------------------------------------------------------
extern "C" void kernel_launch(void* const* d_in, const int* in_sizes, int n_in,
                              void* d_out, int out_size)
{
    const float* x      = (const float*)d_in[0];
    const float* mask   = (const float*)d_in[1];
    const float* qkv_w  = (const float*)d_in[2];
    const float* qkv_b  = (const float*)d_in[3];
    const float* proj_w = (const float*)d_in[4];
    const float* proj_b = (const float*)d_in[5];
    const float* bt     = (const float*)d_in[6];
    float* out = (float*)d_out;

    cudaFuncSetAttribute((const void*)gemm_xres<12, true>,
                         cudaFuncAttributeMaxDynamicSharedMemorySize, GEMM_SMEM);
    cudaFuncSetAttribute((const void*)gemm_xres<4, false>,
                         cudaFuncAttributeMaxDynamicSharedMemorySize, GEMM_SMEM);

    gemm_xres<12, true><<<M_ROWS / 128, 256, GEMM_SMEM>>>(x, qkv_w, qkv_b, nullptr);
    attn_kernel<<<B_WIN * H_NUM, 256>>>(mask, bt);
    gemm_xres<4, false><<<M_ROWS / 128, 256, GEMM_SMEM>>>(nullptr, proj_w, proj_b, out);
}